// round 5
// baseline (speedup 1.0000x reference)
#include <cuda_runtime.h>

#define B_   2
#define N_   2048
#define H_   8
#define DH_  64
#define BH_  (B_ * H_)
#define QMOD 513

// Scratch (device globals; no runtime allocation allowed).
__device__ float g_q[BH_ * N_ * DH_];
__device__ float g_k[BH_ * N_ * DH_];
__device__ float g_v[BH_ * N_ * DH_];
__device__ float g_t[BH_ * N_ * DH_];
__device__ float g_cat[B_ * N_ * H_ * 2 * DH_];   // [b][n][h][128]

// ---------------------------------------------------------------------------
// Kernel 1: qkvt = X[4096,512] @ W_qkv[512,2048], epilogue scatters into
// head-major q/k/v/t buffers [b,h,n,d]. 64x64 block tile, 4x4 micro-tile.
// ---------------------------------------------------------------------------
__global__ __launch_bounds__(256) void k_gemm_qkv(const float* __restrict__ X,
                                                  const float* __restrict__ W)
{
    __shared__ __align__(16) float As[64][17];
    __shared__ __align__(16) float Bs[16][64];
    const int tid  = threadIdx.x;
    const int tx   = tid & 15, ty = tid >> 4;
    const int row0 = blockIdx.y << 6, col0 = blockIdx.x << 6;
    const int la_r = tid >> 2,  la_k = (tid & 3) << 2;
    const int lb_k = tid >> 4,  lb_c = (tid & 15) << 2;

    float acc[4][4] = {{0.f}};

    for (int k0 = 0; k0 < 512; k0 += 16) {
        float4 av = *(const float4*)(X + (row0 + la_r) * 512 + k0 + la_k);
        As[la_r][la_k + 0] = av.x;
        As[la_r][la_k + 1] = av.y;
        As[la_r][la_k + 2] = av.z;
        As[la_r][la_k + 3] = av.w;
        *(float4*)&Bs[lb_k][lb_c] =
            *(const float4*)(W + (k0 + lb_k) * 2048 + col0 + lb_c);
        __syncthreads();
#pragma unroll
        for (int kk = 0; kk < 16; ++kk) {
            float4 b4 = *(const float4*)&Bs[kk][tx << 2];
#pragma unroll
            for (int i = 0; i < 4; ++i) {
                float a = As[(ty << 2) + i][kk];
                acc[i][0] = fmaf(a, b4.x, acc[i][0]);
                acc[i][1] = fmaf(a, b4.y, acc[i][1]);
                acc[i][2] = fmaf(a, b4.z, acc[i][2]);
                acc[i][3] = fmaf(a, b4.w, acc[i][3]);
            }
        }
        __syncthreads();
    }

    // Each 64-wide column tile lies entirely within one section (q/k/v/t)
    // and one head (both are 64-col aligned blocks of the 2048-wide output).
    const int sec = col0 >> 9;
    const int h   = (col0 >> 6) & 7;
    float* dst = (sec == 0) ? g_q : (sec == 1) ? g_k : (sec == 2) ? g_v : g_t;
#pragma unroll
    for (int i = 0; i < 4; ++i) {
        int gr = row0 + (ty << 2) + i;
        int b  = gr >> 11;
        int n  = gr & (N_ - 1);
        float4 v = make_float4(acc[i][0], acc[i][1], acc[i][2], acc[i][3]);
        *(float4*)(dst + (((b << 3) | h) * N_ + n) * DH_ + (tx << 2)) = v;
    }
}

// ---------------------------------------------------------------------------
// Kernel 2: flash attention for attn1 branch.
// Grid: (N/64 q-tiles, B*H). q_eff[i] = q[i mod 513] handled at Q load.
// Online softmax over 32-wide K tiles; output -> g_cat[b][n][h][0..63].
// ---------------------------------------------------------------------------
__global__ __launch_bounds__(256) void k_attn()
{
    __shared__ __align__(16) float Qs[64][65];
    __shared__ __align__(16) float Ks[32][65];
    __shared__ __align__(16) float Vs[32][68];
    __shared__ __align__(16) float Ps[64][33];

    const int tid = threadIdx.x;
    const int tx  = tid & 7;      // 8 groups over S-columns / O d-columns
    const int ty  = tid >> 3;     // 32 groups over 2 q-rows each
    const int bh  = blockIdx.y;
    const int q0  = blockIdx.x << 6;
    const float* Qg = g_q + bh * N_ * DH_;
    const float* Kg = g_k + bh * N_ * DH_;
    const float* Vg = g_v + bh * N_ * DH_;

    // Load Q tile with the mod-513 row remap, pre-scaled by dh^-0.5.
    for (int e = tid; e < 64 * 16; e += 256) {
        int r = e >> 4, c4 = (e & 15) << 2;
        int gn = (q0 + r) % QMOD;
        float4 v = *(const float4*)(Qg + gn * DH_ + c4);
        Qs[r][c4 + 0] = v.x * 0.125f;
        Qs[r][c4 + 1] = v.y * 0.125f;
        Qs[r][c4 + 2] = v.z * 0.125f;
        Qs[r][c4 + 3] = v.w * 0.125f;
    }

    float m[2] = {-1e30f, -1e30f};
    float l[2] = {0.f, 0.f};
    float O[2][8];
#pragma unroll
    for (int r = 0; r < 2; ++r)
#pragma unroll
        for (int c = 0; c < 8; ++c) O[r][c] = 0.f;

    const int i0 = ty << 1;
    const int d0 = tx << 3;
    const int lr = tid >> 4, lc = (tid & 15) << 2;

    for (int kt = 0; kt < N_; kt += 32) {
        __syncthreads();   // previous PV done before overwriting Ks/Vs
#pragma unroll
        for (int q = 0; q < 2; ++q) {
            int r = lr + (q << 4);
            float4 kv = *(const float4*)(Kg + (kt + r) * DH_ + lc);
            Ks[r][lc + 0] = kv.x;
            Ks[r][lc + 1] = kv.y;
            Ks[r][lc + 2] = kv.z;
            Ks[r][lc + 3] = kv.w;
            *(float4*)&Vs[r][lc] = *(const float4*)(Vg + (kt + r) * DH_ + lc);
        }
        __syncthreads();

        // S = Q * K^T for rows i0,i0+1 and cols tx*4..tx*4+3
        float sv[2][4] = {{0.f}};
#pragma unroll 16
        for (int kk = 0; kk < 64; ++kk) {
            float qa = Qs[i0][kk];
            float qb = Qs[i0 + 1][kk];
#pragma unroll
            for (int j = 0; j < 4; ++j) {
                float kv = Ks[(tx << 2) + j][kk];
                sv[0][j] = fmaf(qa, kv, sv[0][j]);
                sv[1][j] = fmaf(qb, kv, sv[1][j]);
            }
        }

        float alpha[2];
#pragma unroll
        for (int r = 0; r < 2; ++r) {
            float mx = fmaxf(fmaxf(sv[r][0], sv[r][1]), fmaxf(sv[r][2], sv[r][3]));
            mx = fmaxf(mx, __shfl_xor_sync(0xffffffffu, mx, 1, 8));
            mx = fmaxf(mx, __shfl_xor_sync(0xffffffffu, mx, 2, 8));
            mx = fmaxf(mx, __shfl_xor_sync(0xffffffffu, mx, 4, 8));
            float mn = fmaxf(m[r], mx);
            alpha[r] = __expf(m[r] - mn);
            m[r] = mn;
            float ps = 0.f;
#pragma unroll
            for (int j = 0; j < 4; ++j) {
                float p = __expf(sv[r][j] - mn);
                Ps[i0 + r][(tx << 2) + j] = p;
                ps += p;
            }
            ps += __shfl_xor_sync(0xffffffffu, ps, 1, 8);
            ps += __shfl_xor_sync(0xffffffffu, ps, 2, 8);
            ps += __shfl_xor_sync(0xffffffffu, ps, 4, 8);
            l[r] = l[r] * alpha[r] + ps;
        }
        __syncthreads();

#pragma unroll
        for (int r = 0; r < 2; ++r)
#pragma unroll
            for (int c = 0; c < 8; ++c) O[r][c] *= alpha[r];

#pragma unroll 8
        for (int j = 0; j < 32; ++j) {
            float p0 = Ps[i0][j];
            float p1 = Ps[i0 + 1][j];
            float4 va = *(const float4*)&Vs[j][d0];
            float4 vb = *(const float4*)&Vs[j][d0 + 4];
            O[0][0] = fmaf(p0, va.x, O[0][0]);
            O[0][1] = fmaf(p0, va.y, O[0][1]);
            O[0][2] = fmaf(p0, va.z, O[0][2]);
            O[0][3] = fmaf(p0, va.w, O[0][3]);
            O[0][4] = fmaf(p0, vb.x, O[0][4]);
            O[0][5] = fmaf(p0, vb.y, O[0][5]);
            O[0][6] = fmaf(p0, vb.z, O[0][6]);
            O[0][7] = fmaf(p0, vb.w, O[0][7]);
            O[1][0] = fmaf(p1, va.x, O[1][0]);
            O[1][1] = fmaf(p1, va.y, O[1][1]);
            O[1][2] = fmaf(p1, va.z, O[1][2]);
            O[1][3] = fmaf(p1, va.w, O[1][3]);
            O[1][4] = fmaf(p1, vb.x, O[1][4]);
            O[1][5] = fmaf(p1, vb.y, O[1][5]);
            O[1][6] = fmaf(p1, vb.z, O[1][6]);
            O[1][7] = fmaf(p1, vb.w, O[1][7]);
        }
    }

    const int b = bh >> 3, h = bh & 7;
#pragma unroll
    for (int r = 0; r < 2; ++r) {
        float inv = 1.f / l[r];
        int n = q0 + i0 + r;
        float* p = g_cat + ((b * N_ + n) * H_ + h) * 128 + d0;
        *(float4*)(p)     = make_float4(O[r][0] * inv, O[r][1] * inv,
                                        O[r][2] * inv, O[r][3] * inv);
        *(float4*)(p + 4) = make_float4(O[r][4] * inv, O[r][5] * inv,
                                        O[r][6] * inv, O[r][7] * inv);
    }
}

// ---------------------------------------------------------------------------
// Kernel 3: out2 = attn2 @ t as two geometric IIR scans per channel.
// attn2[i,j] = r^{|i-j|} / s[j],  s[j] closed-form row sum (symmetric matrix).
// out2[i] = f[i] + g_strict[i];  f fwd recurrence, g bwd recurrence.
// 1024 channels (b,h,d), one thread each. Output -> g_cat[b][n][h][64..127].
// ---------------------------------------------------------------------------
__global__ __launch_bounds__(128) void k_scan()
{
    __shared__ float sinv[N_];
    const int tid = threadIdx.x;
    const float inv_e = 0.36787944117144233f;   // 1/e
    const float r     = 0.69220062755534635f;   // exp(-1/e)
    const float cgeo  = 1.0f / (1.0f - r);
    for (int i = tid; i < N_; i += 128) {
        float s = 1.0f + (r - __expf(-(float)(i + 1) * inv_e)) * cgeo
                       + (r - __expf(-(float)(N_ - i) * inv_e)) * cgeo;
        sinv[i] = 1.0f / s;
    }
    __syncthreads();

    const int ch = (blockIdx.x << 7) + tid;     // 0..1023
    const int d  = ch & 63;
    const int bh = ch >> 6;
    const int b  = bh >> 3, h = bh & 7;
    const float* tp = g_t + bh * N_ * DH_ + d;
    float* cp = g_cat + (b * N_ * H_) * 128 + h * 128 + 64 + d;  // stride 1024/n

    float f = 0.f;
    for (int base = 0; base < N_; base += 16) {
        float u[16];
#pragma unroll
        for (int q = 0; q < 16; ++q)
            u[q] = tp[(base + q) * DH_] * sinv[base + q];
#pragma unroll
        for (int q = 0; q < 16; ++q) {
            f = fmaf(r, f, u[q]);
            cp[(base + q) * 1024] = f;
        }
    }
    float g = 0.f;
    for (int base = N_ - 16; base >= 0; base -= 16) {
        float u[16];
#pragma unroll
        for (int q = 0; q < 16; ++q)
            u[q] = tp[(base + q) * DH_] * sinv[base + q];
#pragma unroll
        for (int q = 15; q >= 0; --q) {
            cp[(base + q) * 1024] += g;       // += strict upper part
            g = r * (u[q] + g);
        }
    }
}

// ---------------------------------------------------------------------------
// Kernel 4: out = g_cat[4096,1024] @ W_out[1024,512] + b_out.
// ---------------------------------------------------------------------------
__global__ __launch_bounds__(256) void k_gemm_out(const float* __restrict__ W,
                                                  const float* __restrict__ bias,
                                                  float* __restrict__ out)
{
    __shared__ __align__(16) float As[64][17];
    __shared__ __align__(16) float Bs[16][64];
    const int tid  = threadIdx.x;
    const int tx   = tid & 15, ty = tid >> 4;
    const int row0 = blockIdx.y << 6, col0 = blockIdx.x << 6;
    const int la_r = tid >> 2,  la_k = (tid & 3) << 2;
    const int lb_k = tid >> 4,  lb_c = (tid & 15) << 2;

    float acc[4][4] = {{0.f}};

    for (int k0 = 0; k0 < 1024; k0 += 16) {
        float4 av = *(const float4*)(g_cat + (row0 + la_r) * 1024 + k0 + la_k);
        As[la_r][la_k + 0] = av.x;
        As[la_r][la_k + 1] = av.y;
        As[la_r][la_k + 2] = av.z;
        As[la_r][la_k + 3] = av.w;
        *(float4*)&Bs[lb_k][lb_c] =
            *(const float4*)(W + (k0 + lb_k) * 512 + col0 + lb_c);
        __syncthreads();
#pragma unroll
        for (int kk = 0; kk < 16; ++kk) {
            float4 b4 = *(const float4*)&Bs[kk][tx << 2];
#pragma unroll
            for (int i = 0; i < 4; ++i) {
                float a = As[(ty << 2) + i][kk];
                acc[i][0] = fmaf(a, b4.x, acc[i][0]);
                acc[i][1] = fmaf(a, b4.y, acc[i][1]);
                acc[i][2] = fmaf(a, b4.z, acc[i][2]);
                acc[i][3] = fmaf(a, b4.w, acc[i][3]);
            }
        }
        __syncthreads();
    }

    float4 bv = *(const float4*)(bias + col0 + (tx << 2));
#pragma unroll
    for (int i = 0; i < 4; ++i) {
        int gr = row0 + (ty << 2) + i;
        float4 v = make_float4(acc[i][0] + bv.x, acc[i][1] + bv.y,
                               acc[i][2] + bv.z, acc[i][3] + bv.w);
        *(float4*)(out + gr * 512 + col0 + (tx << 2)) = v;
    }
}

// ---------------------------------------------------------------------------
extern "C" void kernel_launch(void* const* d_in, const int* in_sizes, int n_in,
                              void* d_out, int out_size)
{
    (void)in_sizes; (void)n_in; (void)out_size;
    const float* x     = (const float*)d_in[0];
    const float* W_qkv = (const float*)d_in[1];
    const float* W_out = (const float*)d_in[2];
    const float* b_out = (const float*)d_in[3];
    float* out = (float*)d_out;

    k_gemm_qkv<<<dim3(32, 64), 256>>>(x, W_qkv);   // qkvt projection + scatter
    k_scan    <<<8, 128>>>();                      // attn2 branch (IIR scans)
    k_attn    <<<dim3(32, 16), 256>>>();           // attn1 branch (flash)
    k_gemm_out<<<dim3(8, 64), 256>>>(W_out, b_out, out);
}

// round 7
// speedup vs baseline: 3.4751x; 3.4751x over previous
#include <cuda_runtime.h>

#define B_   2
#define N_   2048
#define H_   8
#define DH_  64
#define BH_  16
#define QMOD 513

// Scratch (device globals; no runtime allocation allowed).
__device__ float g_q[BH_ * N_ * DH_];
__device__ float g_k[BH_ * N_ * DH_];
__device__ float g_v[BH_ * N_ * DH_];
__device__ float g_t[BH_ * N_ * DH_];
__device__ float g_cat[B_ * N_ * H_ * 2 * DH_];   // [b][n][h][128]

// ---------------------------------------------------------------------------
// TF32 helpers
// ---------------------------------------------------------------------------
__device__ __forceinline__ float to_tf32(float x) {
    float r;
    asm("cvt.rna.tf32.f32 %0, %1;" : "=f"(r) : "f"(x));
    return r;
}

// D = A(16x8,row) * B(8x8,col) + C, tf32 inputs, f32 accumulate.
__device__ __forceinline__ void mma8(float4& d, const unsigned* a,
                                     const unsigned* b, const float4& c) {
    asm volatile(
        "mma.sync.aligned.m16n8k8.row.col.f32.tf32.tf32.f32 "
        "{%0,%1,%2,%3}, {%4,%5,%6,%7}, {%8,%9}, {%10,%11,%12,%13};\n"
        : "=f"(d.x), "=f"(d.y), "=f"(d.z), "=f"(d.w)
        : "r"(a[0]), "r"(a[1]), "r"(a[2]), "r"(a[3]),
          "r"(b[0]), "r"(b[1]),
          "f"(c.x), "f"(c.y), "f"(c.z), "f"(c.w));
}

// ---------------------------------------------------------------------------
// Kernel 1: qkvt = X[4096,512] @ W_qkv[512,2048]  (tf32 MMA, 128x128 tile)
// Epilogue scatters into head-major q/k/v/t [bh][n][d].
// ---------------------------------------------------------------------------
__global__ __launch_bounds__(256) void k_gemm_qkv(const float* __restrict__ X,
                                                  const float* __restrict__ W)
{
    __shared__ float As[128][36];    // [m][k]  pad: 4r+c conflict-free frags
    __shared__ float Bs[32][136];    // [k][n]  pad: 8r+c conflict-free frags
    const int tid  = threadIdx.x;
    const int lane = tid & 31, warp = tid >> 5;
    const int gid  = lane >> 2, tig = lane & 3;
    const int row0 = blockIdx.y << 7, col0 = blockIdx.x << 7;
    const int wm = (warp & 3) << 5;     // warp m-offset: 0/32/64/96
    const int wn = (warp >> 2) << 6;    // warp n-offset: 0/64

    float4 acc[2][8];
#pragma unroll
    for (int i = 0; i < 2; ++i)
#pragma unroll
        for (int j = 0; j < 8; ++j) acc[i][j] = make_float4(0.f, 0.f, 0.f, 0.f);

    const int ar_ = tid >> 3, ac_ = (tid & 7) << 2;   // A: 32 rows/pass
    const int br_ = tid >> 5, bc_ = (tid & 31) << 2;  // B: 8 rows/pass

    for (int k0 = 0; k0 < 512; k0 += 32) {
#pragma unroll
        for (int p = 0; p < 4; ++p) {
            int r = ar_ + (p << 5);
            float4 v = *(const float4*)(X + (row0 + r) * 512 + k0 + ac_);
            v.x = to_tf32(v.x); v.y = to_tf32(v.y);
            v.z = to_tf32(v.z); v.w = to_tf32(v.w);
            *(float4*)&As[r][ac_] = v;
        }
#pragma unroll
        for (int p = 0; p < 4; ++p) {
            int r = br_ + (p << 3);
            float4 v = *(const float4*)(W + (k0 + r) * 2048 + col0 + bc_);
            v.x = to_tf32(v.x); v.y = to_tf32(v.y);
            v.z = to_tf32(v.z); v.w = to_tf32(v.w);
            *(float4*)&Bs[r][bc_] = v;
        }
        __syncthreads();

#pragma unroll
        for (int ks = 0; ks < 4; ++ks) {
            const int kk = ks << 3;
            unsigned a[2][4], b[8][2];
#pragma unroll
            for (int mt = 0; mt < 2; ++mt) {
                int r = wm + (mt << 4) + gid;
                a[mt][0] = __float_as_uint(As[r][kk + tig]);
                a[mt][1] = __float_as_uint(As[r + 8][kk + tig]);
                a[mt][2] = __float_as_uint(As[r][kk + tig + 4]);
                a[mt][3] = __float_as_uint(As[r + 8][kk + tig + 4]);
            }
#pragma unroll
            for (int nt = 0; nt < 8; ++nt) {
                int c = wn + (nt << 3) + gid;
                b[nt][0] = __float_as_uint(Bs[kk + tig][c]);
                b[nt][1] = __float_as_uint(Bs[kk + tig + 4][c]);
            }
#pragma unroll
            for (int mt = 0; mt < 2; ++mt)
#pragma unroll
                for (int nt = 0; nt < 8; ++nt)
                    mma8(acc[mt][nt], a[mt], b[nt], acc[mt][nt]);
        }
        __syncthreads();
    }

    // Scatter epilogue: section (q/k/v/t), head, d from the global column.
#pragma unroll
    for (int mt = 0; mt < 2; ++mt) {
        int gr0 = row0 + wm + (mt << 4) + gid;
        int gr1 = gr0 + 8;
        int b0i = gr0 >> 11, n0i = gr0 & (N_ - 1);
        int b1i = gr1 >> 11, n1i = gr1 & (N_ - 1);
#pragma unroll
        for (int nt = 0; nt < 8; ++nt) {
            int gc  = col0 + wn + (nt << 3) + (tig << 1);
            int sec = gc >> 9, h = (gc >> 6) & 7, d = gc & 63;
            float* dst = (sec == 0) ? g_q : (sec == 1) ? g_k
                       : (sec == 2) ? g_v : g_t;
            *(float2*)(dst + (((b0i << 3) | h) * N_ + n0i) * DH_ + d)
                = make_float2(acc[mt][nt].x, acc[mt][nt].y);
            *(float2*)(dst + (((b1i << 3) | h) * N_ + n1i) * DH_ + d)
                = make_float2(acc[mt][nt].z, acc[mt][nt].w);
        }
    }
}

// ---------------------------------------------------------------------------
// Kernel 2: flash attention (attn1) with tf32 MMA.
// Grid (N/64, BH), 128 threads (4 warps). Each warp owns 16 q-rows.
// K chunk = 32 tokens. Output -> g_cat[b][n][h][0..63].
// ---------------------------------------------------------------------------
__global__ __launch_bounds__(128) void k_attn()
{
    __shared__ float Qs[64][68];   // A operand [q][d]
    __shared__ float Ks[32][68];   // B operand for S: [token][d]
    __shared__ float Vs[32][72];   // B operand for PV: [token][d]
    __shared__ float Ps[64][36];   // A operand for PV: [q][token]

    const int tid  = threadIdx.x;
    const int lane = tid & 31, warp = tid >> 5;
    const int gid  = lane >> 2, tig = lane & 3;
    const int bh   = blockIdx.y;
    const int q0   = blockIdx.x << 6;
    const float* Qg = g_q + bh * N_ * DH_;
    const float* Kg = g_k + bh * N_ * DH_;
    const float* Vg = g_v + bh * N_ * DH_;

    // Load Q tile: mod-513 remap, *dh^-0.5, tf32-rounded.
    const int lr = tid >> 4, lc = (tid & 15) << 2;
#pragma unroll
    for (int p = 0; p < 8; ++p) {
        int r  = lr + (p << 3);
        int gn = (q0 + r) % QMOD;
        float4 v = *(const float4*)(Qg + gn * DH_ + lc);
        Qs[r][lc + 0] = to_tf32(v.x * 0.125f);
        Qs[r][lc + 1] = to_tf32(v.y * 0.125f);
        Qs[r][lc + 2] = to_tf32(v.z * 0.125f);
        Qs[r][lc + 3] = to_tf32(v.w * 0.125f);
    }

    float4 o[8];
#pragma unroll
    for (int nt = 0; nt < 8; ++nt) o[nt] = make_float4(0.f, 0.f, 0.f, 0.f);
    float m0 = -1e30f, m1 = -1e30f, l0 = 0.f, l1 = 0.f;
    const int wq = warp << 4;

    const int kvr = tid >> 4, kvc = (tid & 15) << 2;

    for (int kt = 0; kt < N_; kt += 32) {
        __syncthreads();               // prev PV done before overwriting K/V
#pragma unroll
        for (int p = 0; p < 4; ++p) {
            int r = kvr + (p << 3);
            float4 kv = *(const float4*)(Kg + (kt + r) * DH_ + kvc);
            kv.x = to_tf32(kv.x); kv.y = to_tf32(kv.y);
            kv.z = to_tf32(kv.z); kv.w = to_tf32(kv.w);
            *(float4*)&Ks[r][kvc] = kv;
            float4 vv = *(const float4*)(Vg + (kt + r) * DH_ + kvc);
            vv.x = to_tf32(vv.x); vv.y = to_tf32(vv.y);
            vv.z = to_tf32(vv.z); vv.w = to_tf32(vv.w);
            *(float4*)&Vs[r][kvc] = vv;
        }
        __syncthreads();

        // ---- S = Q * K^T  (16 rows x 32 cols per warp) ----
        float4 s[4];
#pragma unroll
        for (int nt = 0; nt < 4; ++nt) s[nt] = make_float4(0.f, 0.f, 0.f, 0.f);
#pragma unroll
        for (int ks = 0; ks < 8; ++ks) {
            const int kk = ks << 3;
            unsigned a[4], b[4][2];
            int r = wq + gid;
            a[0] = __float_as_uint(Qs[r][kk + tig]);
            a[1] = __float_as_uint(Qs[r + 8][kk + tig]);
            a[2] = __float_as_uint(Qs[r][kk + tig + 4]);
            a[3] = __float_as_uint(Qs[r + 8][kk + tig + 4]);
#pragma unroll
            for (int nt = 0; nt < 4; ++nt) {
                int c = (nt << 3) + gid;           // token index
                b[nt][0] = __float_as_uint(Ks[c][kk + tig]);
                b[nt][1] = __float_as_uint(Ks[c][kk + tig + 4]);
            }
#pragma unroll
            for (int nt = 0; nt < 4; ++nt) mma8(s[nt], a, b[nt], s[nt]);
        }

        // ---- online softmax (rows: r0 = wq+gid -> .x/.y, r1 = +8 -> .z/.w)
        float mx0 = -1e30f, mx1 = -1e30f;
#pragma unroll
        for (int nt = 0; nt < 4; ++nt) {
            mx0 = fmaxf(mx0, fmaxf(s[nt].x, s[nt].y));
            mx1 = fmaxf(mx1, fmaxf(s[nt].z, s[nt].w));
        }
        mx0 = fmaxf(mx0, __shfl_xor_sync(0xffffffffu, mx0, 1));
        mx0 = fmaxf(mx0, __shfl_xor_sync(0xffffffffu, mx0, 2));
        mx1 = fmaxf(mx1, __shfl_xor_sync(0xffffffffu, mx1, 1));
        mx1 = fmaxf(mx1, __shfl_xor_sync(0xffffffffu, mx1, 2));
        float mn0 = fmaxf(m0, mx0), mn1 = fmaxf(m1, mx1);
        float al0 = __expf(m0 - mn0), al1 = __expf(m1 - mn1);
        m0 = mn0; m1 = mn1;
        float ps0 = 0.f, ps1 = 0.f;
#pragma unroll
        for (int nt = 0; nt < 4; ++nt) {
            float px = __expf(s[nt].x - mn0), py = __expf(s[nt].y - mn0);
            float pz = __expf(s[nt].z - mn1), pw = __expf(s[nt].w - mn1);
            ps0 += px + py; ps1 += pz + pw;
            int c = (nt << 3) + (tig << 1);
            *(float2*)&Ps[wq + gid][c]     = make_float2(to_tf32(px), to_tf32(py));
            *(float2*)&Ps[wq + gid + 8][c] = make_float2(to_tf32(pz), to_tf32(pw));
        }
        ps0 += __shfl_xor_sync(0xffffffffu, ps0, 1);
        ps0 += __shfl_xor_sync(0xffffffffu, ps0, 2);
        ps1 += __shfl_xor_sync(0xffffffffu, ps1, 1);
        ps1 += __shfl_xor_sync(0xffffffffu, ps1, 2);
        l0 = l0 * al0 + ps0;
        l1 = l1 * al1 + ps1;
#pragma unroll
        for (int nt = 0; nt < 8; ++nt) {
            o[nt].x *= al0; o[nt].y *= al0;
            o[nt].z *= al1; o[nt].w *= al1;
        }
        __syncwarp();   // Ps rows are warp-private: warp-level visibility only

        // ---- O += P * V  (16 rows x 64 d per warp) ----
#pragma unroll
        for (int ks = 0; ks < 4; ++ks) {
            const int kk = ks << 3;
            unsigned a[4], b[8][2];
            int r = wq + gid;
            a[0] = __float_as_uint(Ps[r][kk + tig]);
            a[1] = __float_as_uint(Ps[r + 8][kk + tig]);
            a[2] = __float_as_uint(Ps[r][kk + tig + 4]);
            a[3] = __float_as_uint(Ps[r + 8][kk + tig + 4]);
#pragma unroll
            for (int nt = 0; nt < 8; ++nt) {
                int c = (nt << 3) + gid;           // d index
                b[nt][0] = __float_as_uint(Vs[kk + tig][c]);
                b[nt][1] = __float_as_uint(Vs[kk + tig + 4][c]);
            }
#pragma unroll
            for (int nt = 0; nt < 8; ++nt) mma8(o[nt], a, b[nt], o[nt]);
        }
    }

    // ---- final normalize + store ----
    float inv0 = 1.f / l0, inv1 = 1.f / l1;
    const int bb = bh >> 3, h = bh & 7;
    int nr0 = q0 + wq + gid;
    float* base0 = g_cat + ((bb * N_ + nr0) * H_ + h) * 128;
    float* base1 = g_cat + ((bb * N_ + nr0 + 8) * H_ + h) * 128;
#pragma unroll
    for (int nt = 0; nt < 8; ++nt) {
        int d = (nt << 3) + (tig << 1);
        *(float2*)(base0 + d) = make_float2(o[nt].x * inv0, o[nt].y * inv0);
        *(float2*)(base1 + d) = make_float2(o[nt].z * inv1, o[nt].w * inv1);
    }
}

// ---------------------------------------------------------------------------
// Kernel 3: out2 = attn2 @ t as two geometric IIR scans per channel (exact).
// ---------------------------------------------------------------------------
__global__ __launch_bounds__(128) void k_scan()
{
    __shared__ float sinv[N_];
    const int tid = threadIdx.x;
    const float inv_e = 0.36787944117144233f;   // 1/e
    const float r     = 0.69220062755534635f;   // exp(-1/e)
    const float cgeo  = 1.0f / (1.0f - r);
    for (int i = tid; i < N_; i += 128) {
        float s = 1.0f + (r - __expf(-(float)(i + 1) * inv_e)) * cgeo
                       + (r - __expf(-(float)(N_ - i) * inv_e)) * cgeo;
        sinv[i] = 1.0f / s;
    }
    __syncthreads();

    const int ch = (blockIdx.x << 7) + tid;     // 0..1023
    const int d  = ch & 63;
    const int bh = ch >> 6;
    const int b  = bh >> 3, h = bh & 7;
    const float* tp = g_t + bh * N_ * DH_ + d;
    float* cp = g_cat + (b * N_ * H_) * 128 + h * 128 + 64 + d;

    float f = 0.f;
    for (int base = 0; base < N_; base += 16) {
        float u[16];
#pragma unroll
        for (int q = 0; q < 16; ++q)
            u[q] = tp[(base + q) * DH_] * sinv[base + q];
#pragma unroll
        for (int q = 0; q < 16; ++q) {
            f = fmaf(r, f, u[q]);
            cp[(base + q) * 1024] = f;
        }
    }
    float g = 0.f;
    for (int base = N_ - 16; base >= 0; base -= 16) {
        float u[16];
#pragma unroll
        for (int q = 0; q < 16; ++q)
            u[q] = tp[(base + q) * DH_] * sinv[base + q];
#pragma unroll
        for (int q = 15; q >= 0; --q) {
            cp[(base + q) * 1024] += g;
            g = r * (u[q] + g);
        }
    }
}

// ---------------------------------------------------------------------------
// Kernel 4: out = g_cat[4096,1024] @ W_out[1024,512] + b_out (tf32 MMA)
// ---------------------------------------------------------------------------
__global__ __launch_bounds__(256) void k_gemm_out(const float* __restrict__ W,
                                                  const float* __restrict__ bias,
                                                  float* __restrict__ out)
{
    __shared__ float As[128][36];
    __shared__ float Bs[32][136];
    const int tid  = threadIdx.x;
    const int lane = tid & 31, warp = tid >> 5;
    const int gid  = lane >> 2, tig = lane & 3;
    const int row0 = blockIdx.y << 7, col0 = blockIdx.x << 7;
    const int wm = (warp & 3) << 5;
    const int wn = (warp >> 2) << 6;

    float4 acc[2][8];
#pragma unroll
    for (int i = 0; i < 2; ++i)
#pragma unroll
        for (int j = 0; j < 8; ++j) acc[i][j] = make_float4(0.f, 0.f, 0.f, 0.f);

    const int ar_ = tid >> 3, ac_ = (tid & 7) << 2;
    const int br_ = tid >> 5, bc_ = (tid & 31) << 2;

    for (int k0 = 0; k0 < 1024; k0 += 32) {
#pragma unroll
        for (int p = 0; p < 4; ++p) {
            int r = ar_ + (p << 5);
            float4 v = *(const float4*)(g_cat + (row0 + r) * 1024 + k0 + ac_);
            v.x = to_tf32(v.x); v.y = to_tf32(v.y);
            v.z = to_tf32(v.z); v.w = to_tf32(v.w);
            *(float4*)&As[r][ac_] = v;
        }
#pragma unroll
        for (int p = 0; p < 4; ++p) {
            int r = br_ + (p << 3);
            float4 v = *(const float4*)(W + (k0 + r) * 512 + col0 + bc_);
            v.x = to_tf32(v.x); v.y = to_tf32(v.y);
            v.z = to_tf32(v.z); v.w = to_tf32(v.w);
            *(float4*)&Bs[r][bc_] = v;
        }
        __syncthreads();

#pragma unroll
        for (int ks = 0; ks < 4; ++ks) {
            const int kk = ks << 3;
            unsigned a[2][4], b[8][2];
#pragma unroll
            for (int mt = 0; mt < 2; ++mt) {
                int r = wm + (mt << 4) + gid;
                a[mt][0] = __float_as_uint(As[r][kk + tig]);
                a[mt][1] = __float_as_uint(As[r + 8][kk + tig]);
                a[mt][2] = __float_as_uint(As[r][kk + tig + 4]);
                a[mt][3] = __float_as_uint(As[r + 8][kk + tig + 4]);
            }
#pragma unroll
            for (int nt = 0; nt < 8; ++nt) {
                int c = wn + (nt << 3) + gid;
                b[nt][0] = __float_as_uint(Bs[kk + tig][c]);
                b[nt][1] = __float_as_uint(Bs[kk + tig + 4][c]);
            }
#pragma unroll
            for (int mt = 0; mt < 2; ++mt)
#pragma unroll
                for (int nt = 0; nt < 8; ++nt)
                    mma8(acc[mt][nt], a[mt], b[nt], acc[mt][nt]);
        }
        __syncthreads();
    }

#pragma unroll
    for (int mt = 0; mt < 2; ++mt) {
        int gr0 = row0 + wm + (mt << 4) + gid;
        int gr1 = gr0 + 8;
#pragma unroll
        for (int nt = 0; nt < 8; ++nt) {
            int gc = col0 + wn + (nt << 3) + (tig << 1);
            float2 bv = *(const float2*)(bias + gc);
            *(float2*)(out + gr0 * 512 + gc)
                = make_float2(acc[mt][nt].x + bv.x, acc[mt][nt].y + bv.y);
            *(float2*)(out + gr1 * 512 + gc)
                = make_float2(acc[mt][nt].z + bv.x, acc[mt][nt].w + bv.y);
        }
    }
}

// ---------------------------------------------------------------------------
extern "C" void kernel_launch(void* const* d_in, const int* in_sizes, int n_in,
                              void* d_out, int out_size)
{
    (void)in_sizes; (void)n_in; (void)out_size;
    const float* x     = (const float*)d_in[0];
    const float* W_qkv = (const float*)d_in[1];
    const float* W_out = (const float*)d_in[2];
    const float* b_out = (const float*)d_in[3];
    float* out = (float*)d_out;

    k_gemm_qkv<<<dim3(16, 32), 256>>>(x, W_qkv);   // qkvt projection (tf32 MMA)
    k_scan    <<<8, 128>>>();                      // attn2 branch (exact IIR)
    k_attn    <<<dim3(32, 16), 128>>>();           // attn1 flash (tf32 MMA)
    k_gemm_out<<<dim3(4, 32), 256>>>(W_out, b_out, out);
}

// round 10
// speedup vs baseline: 4.7569x; 1.3688x over previous
#include <cuda_runtime.h>

#define B_   2
#define N_   2048
#define H_   8
#define DH_  64
#define BH_  16
#define QMOD 513

// Scratch (device globals; no runtime allocation allowed).
__device__ float g_q[BH_ * N_ * DH_];
__device__ float g_k[BH_ * N_ * DH_];
__device__ float g_v[BH_ * N_ * DH_];
__device__ float g_t[BH_ * N_ * DH_];
__device__ float g_cat[B_ * N_ * H_ * 2 * DH_];   // [b][n][h][128]

// ---------------------------------------------------------------------------
// TF32 helpers
// ---------------------------------------------------------------------------
__device__ __forceinline__ float to_tf32(float x) {
    float r;
    asm("cvt.rna.tf32.f32 %0, %1;" : "=f"(r) : "f"(x));
    return r;
}
__device__ __forceinline__ float4 cvt4(float4 v) {
    v.x = to_tf32(v.x); v.y = to_tf32(v.y);
    v.z = to_tf32(v.z); v.w = to_tf32(v.w);
    return v;
}

// D = A(16x8,row) * B(8x8,col) + C, tf32 inputs, f32 accumulate.
__device__ __forceinline__ void mma8(float4& d, const unsigned* a,
                                     const unsigned* b, const float4& c) {
    asm volatile(
        "mma.sync.aligned.m16n8k8.row.col.f32.tf32.tf32.f32 "
        "{%0,%1,%2,%3}, {%4,%5,%6,%7}, {%8,%9}, {%10,%11,%12,%13};\n"
        : "=f"(d.x), "=f"(d.y), "=f"(d.z), "=f"(d.w)
        : "r"(a[0]), "r"(a[1]), "r"(a[2]), "r"(a[3]),
          "r"(b[0]), "r"(b[1]),
          "f"(c.x), "f"(c.y), "f"(c.z), "f"(c.w));
}

// ---------------------------------------------------------------------------
// Kernel 1: qkvt = X[4096,512] @ W_qkv[512,2048]  (tf32 MMA, 128x128 tile,
// double-buffered SMEM + register-staged prefetch).
// ---------------------------------------------------------------------------
__global__ __launch_bounds__(256) void k_gemm_qkv(const float* __restrict__ X,
                                                  const float* __restrict__ W)
{
    __shared__ float As[2][128][36];
    __shared__ float Bs[2][32][136];
    const int tid  = threadIdx.x;
    const int lane = tid & 31, warp = tid >> 5;
    const int gid  = lane >> 2, tig = lane & 3;
    const int row0 = blockIdx.y << 7, col0 = blockIdx.x << 7;
    const int wm = (warp & 3) << 5;
    const int wn = (warp >> 2) << 6;

    float4 acc[2][8];
#pragma unroll
    for (int i = 0; i < 2; ++i)
#pragma unroll
        for (int j = 0; j < 8; ++j) acc[i][j] = make_float4(0.f, 0.f, 0.f, 0.f);

    const int ar_ = tid >> 3, ac_ = (tid & 7) << 2;   // A: 32 rows/pass
    const int br_ = tid >> 5, bc_ = (tid & 31) << 2;  // B: 8 rows/pass

    float4 ra[4], rb[4];
#pragma unroll
    for (int p = 0; p < 4; ++p)
        ra[p] = *(const float4*)(X + (row0 + ar_ + (p << 5)) * 512 + ac_);
#pragma unroll
    for (int p = 0; p < 4; ++p)
        rb[p] = *(const float4*)(W + (br_ + (p << 3)) * 2048 + col0 + bc_);
#pragma unroll
    for (int p = 0; p < 4; ++p)
        *(float4*)&As[0][ar_ + (p << 5)][ac_] = cvt4(ra[p]);
#pragma unroll
    for (int p = 0; p < 4; ++p)
        *(float4*)&Bs[0][br_ + (p << 3)][bc_] = cvt4(rb[p]);
    __syncthreads();

    int buf = 0;
    for (int k0 = 0; k0 < 512; k0 += 32) {
        const bool nxt = (k0 + 32) < 512;
        if (nxt) {
#pragma unroll
            for (int p = 0; p < 4; ++p)
                ra[p] = *(const float4*)(X + (row0 + ar_ + (p << 5)) * 512
                                         + k0 + 32 + ac_);
#pragma unroll
            for (int p = 0; p < 4; ++p)
                rb[p] = *(const float4*)(W + (k0 + 32 + br_ + (p << 3)) * 2048
                                         + col0 + bc_);
        }
        float (*Ac)[36]  = As[buf];
        float (*Bc)[136] = Bs[buf];
#pragma unroll
        for (int ks = 0; ks < 4; ++ks) {
            const int kk = ks << 3;
            unsigned a[2][4], b[8][2];
#pragma unroll
            for (int mt = 0; mt < 2; ++mt) {
                int r = wm + (mt << 4) + gid;
                a[mt][0] = __float_as_uint(Ac[r][kk + tig]);
                a[mt][1] = __float_as_uint(Ac[r + 8][kk + tig]);
                a[mt][2] = __float_as_uint(Ac[r][kk + tig + 4]);
                a[mt][3] = __float_as_uint(Ac[r + 8][kk + tig + 4]);
            }
#pragma unroll
            for (int nt = 0; nt < 8; ++nt) {
                int c = wn + (nt << 3) + gid;
                b[nt][0] = __float_as_uint(Bc[kk + tig][c]);
                b[nt][1] = __float_as_uint(Bc[kk + tig + 4][c]);
            }
#pragma unroll
            for (int mt = 0; mt < 2; ++mt)
#pragma unroll
                for (int nt = 0; nt < 8; ++nt)
                    mma8(acc[mt][nt], a[mt], b[nt], acc[mt][nt]);
        }
        if (nxt) {
            float (*An)[36]  = As[buf ^ 1];
            float (*Bn)[136] = Bs[buf ^ 1];
#pragma unroll
            for (int p = 0; p < 4; ++p)
                *(float4*)&An[ar_ + (p << 5)][ac_] = cvt4(ra[p]);
#pragma unroll
            for (int p = 0; p < 4; ++p)
                *(float4*)&Bn[br_ + (p << 3)][bc_] = cvt4(rb[p]);
        }
        __syncthreads();
        buf ^= 1;
    }

    // Scatter epilogue: section (q/k/v/t), head, d from the global column.
#pragma unroll
    for (int mt = 0; mt < 2; ++mt) {
        int gr0 = row0 + wm + (mt << 4) + gid;
        int gr1 = gr0 + 8;
        int b0i = gr0 >> 11, n0i = gr0 & (N_ - 1);
        int b1i = gr1 >> 11, n1i = gr1 & (N_ - 1);
#pragma unroll
        for (int nt = 0; nt < 8; ++nt) {
            int gc  = col0 + wn + (nt << 3) + (tig << 1);
            int sec = gc >> 9, h = (gc >> 6) & 7, d = gc & 63;
            float* dst = (sec == 0) ? g_q : (sec == 1) ? g_k
                       : (sec == 2) ? g_v : g_t;
            *(float2*)(dst + (((b0i << 3) | h) * N_ + n0i) * DH_ + d)
                = make_float2(acc[mt][nt].x, acc[mt][nt].y);
            *(float2*)(dst + (((b1i << 3) | h) * N_ + n1i) * DH_ + d)
                = make_float2(acc[mt][nt].z, acc[mt][nt].w);
        }
    }
}

// ---------------------------------------------------------------------------
// Kernel 2: flash attention (attn1) with tf32 MMA.
// Q fragments hoisted to registers (loop-invariant); K/V double-buffered
// with register-staged prefetch. Grid (N/64, BH), 128 threads.
// ---------------------------------------------------------------------------
__global__ __launch_bounds__(128) void k_attn()
{
    __shared__ float Qs[64][68];       // A operand [q][d]
    __shared__ float Ks[2][32][68];    // B operand for S: [token][d]
    __shared__ float Vs[2][32][72];    // B operand for PV: [token][d]
    __shared__ float Ps[64][36];       // A operand for PV: [q][token]

    const int tid  = threadIdx.x;
    const int lane = tid & 31, warp = tid >> 5;
    const int gid  = lane >> 2, tig = lane & 3;
    const int bh   = blockIdx.y;
    const int q0   = blockIdx.x << 6;
    const float* Qg = g_q + bh * N_ * DH_;
    const float* Kg = g_k + bh * N_ * DH_;
    const float* Vg = g_v + bh * N_ * DH_;

    const int kvr = tid >> 4, kvc = (tid & 15) << 2;

    // Issue K/V chunk-0 global loads early (latency hidden under Q load).
    float4 kreg[4], vreg[4];
#pragma unroll
    for (int p = 0; p < 4; ++p) {
        int r = kvr + (p << 3);
        kreg[p] = *(const float4*)(Kg + r * DH_ + kvc);
        vreg[p] = *(const float4*)(Vg + r * DH_ + kvc);
    }

    // Load Q tile: mod-513 remap, *dh^-0.5, tf32-rounded.
    const int lr = tid >> 4, lc = (tid & 15) << 2;
#pragma unroll
    for (int p = 0; p < 8; ++p) {
        int r  = lr + (p << 3);
        int gn = (q0 + r) % QMOD;
        float4 v = *(const float4*)(Qg + gn * DH_ + lc);
        Qs[r][lc + 0] = to_tf32(v.x * 0.125f);
        Qs[r][lc + 1] = to_tf32(v.y * 0.125f);
        Qs[r][lc + 2] = to_tf32(v.z * 0.125f);
        Qs[r][lc + 3] = to_tf32(v.w * 0.125f);
    }
#pragma unroll
    for (int p = 0; p < 4; ++p) {
        int r = kvr + (p << 3);
        *(float4*)&Ks[0][r][kvc] = cvt4(kreg[p]);
        *(float4*)&Vs[0][r][kvc] = cvt4(vreg[p]);
    }
    __syncthreads();

    const int wq = warp << 4;

    // Hoist Q fragments: loop-invariant across all kt chunks.
    unsigned qf[8][4];
#pragma unroll
    for (int ks = 0; ks < 8; ++ks) {
        const int kk = ks << 3;
        int r = wq + gid;
        qf[ks][0] = __float_as_uint(Qs[r][kk + tig]);
        qf[ks][1] = __float_as_uint(Qs[r + 8][kk + tig]);
        qf[ks][2] = __float_as_uint(Qs[r][kk + tig + 4]);
        qf[ks][3] = __float_as_uint(Qs[r + 8][kk + tig + 4]);
    }

    float4 o[8];
#pragma unroll
    for (int nt = 0; nt < 8; ++nt) o[nt] = make_float4(0.f, 0.f, 0.f, 0.f);
    float m0 = -1e30f, m1 = -1e30f, l0 = 0.f, l1 = 0.f;

    int buf = 0;
    for (int kt = 0; kt < N_; kt += 32) {
        const bool nxt = (kt + 32) < N_;
        if (nxt) {
#pragma unroll
            for (int p = 0; p < 4; ++p) {
                int r = kvr + (p << 3);
                kreg[p] = *(const float4*)(Kg + (kt + 32 + r) * DH_ + kvc);
                vreg[p] = *(const float4*)(Vg + (kt + 32 + r) * DH_ + kvc);
            }
        }
        float (*Kc)[68] = Ks[buf];
        float (*Vc)[72] = Vs[buf];

        // ---- S = Q * K^T  (16 rows x 32 cols per warp) ----
        float4 s[4];
#pragma unroll
        for (int nt = 0; nt < 4; ++nt) s[nt] = make_float4(0.f, 0.f, 0.f, 0.f);
#pragma unroll
        for (int ks = 0; ks < 8; ++ks) {
            const int kk = ks << 3;
            unsigned b[4][2];
#pragma unroll
            for (int nt = 0; nt < 4; ++nt) {
                int c = (nt << 3) + gid;           // token index
                b[nt][0] = __float_as_uint(Kc[c][kk + tig]);
                b[nt][1] = __float_as_uint(Kc[c][kk + tig + 4]);
            }
#pragma unroll
            for (int nt = 0; nt < 4; ++nt) mma8(s[nt], qf[ks], b[nt], s[nt]);
        }

        // ---- online softmax (rows: r0 = wq+gid -> .x/.y, r1 = +8 -> .z/.w)
        float mx0 = -1e30f, mx1 = -1e30f;
#pragma unroll
        for (int nt = 0; nt < 4; ++nt) {
            mx0 = fmaxf(mx0, fmaxf(s[nt].x, s[nt].y));
            mx1 = fmaxf(mx1, fmaxf(s[nt].z, s[nt].w));
        }
        mx0 = fmaxf(mx0, __shfl_xor_sync(0xffffffffu, mx0, 1));
        mx0 = fmaxf(mx0, __shfl_xor_sync(0xffffffffu, mx0, 2));
        mx1 = fmaxf(mx1, __shfl_xor_sync(0xffffffffu, mx1, 1));
        mx1 = fmaxf(mx1, __shfl_xor_sync(0xffffffffu, mx1, 2));
        float mn0 = fmaxf(m0, mx0), mn1 = fmaxf(m1, mx1);
        float al0 = __expf(m0 - mn0), al1 = __expf(m1 - mn1);
        m0 = mn0; m1 = mn1;
        float ps0 = 0.f, ps1 = 0.f;
#pragma unroll
        for (int nt = 0; nt < 4; ++nt) {
            float px = __expf(s[nt].x - mn0), py = __expf(s[nt].y - mn0);
            float pz = __expf(s[nt].z - mn1), pw = __expf(s[nt].w - mn1);
            ps0 += px + py; ps1 += pz + pw;
            int c = (nt << 3) + (tig << 1);
            *(float2*)&Ps[wq + gid][c]     = make_float2(to_tf32(px), to_tf32(py));
            *(float2*)&Ps[wq + gid + 8][c] = make_float2(to_tf32(pz), to_tf32(pw));
        }
        ps0 += __shfl_xor_sync(0xffffffffu, ps0, 1);
        ps0 += __shfl_xor_sync(0xffffffffu, ps0, 2);
        ps1 += __shfl_xor_sync(0xffffffffu, ps1, 1);
        ps1 += __shfl_xor_sync(0xffffffffu, ps1, 2);
        l0 = l0 * al0 + ps0;
        l1 = l1 * al1 + ps1;
#pragma unroll
        for (int nt = 0; nt < 8; ++nt) {
            o[nt].x *= al0; o[nt].y *= al0;
            o[nt].z *= al1; o[nt].w *= al1;
        }
        __syncwarp();   // Ps rows are warp-private: warp-level visibility only

        // ---- O += P * V  (16 rows x 64 d per warp) ----
#pragma unroll
        for (int ks = 0; ks < 4; ++ks) {
            const int kk = ks << 3;
            unsigned a[4], b[8][2];
            int r = wq + gid;
            a[0] = __float_as_uint(Ps[r][kk + tig]);
            a[1] = __float_as_uint(Ps[r + 8][kk + tig]);
            a[2] = __float_as_uint(Ps[r][kk + tig + 4]);
            a[3] = __float_as_uint(Ps[r + 8][kk + tig + 4]);
#pragma unroll
            for (int nt = 0; nt < 8; ++nt) {
                int c = (nt << 3) + gid;           // d index
                b[nt][0] = __float_as_uint(Vc[kk + tig][c]);
                b[nt][1] = __float_as_uint(Vc[kk + tig + 4][c]);
            }
#pragma unroll
            for (int nt = 0; nt < 8; ++nt) mma8(o[nt], a, b[nt], o[nt]);
        }

        if (nxt) {
            float (*Kn)[68] = Ks[buf ^ 1];
            float (*Vn)[72] = Vs[buf ^ 1];
#pragma unroll
            for (int p = 0; p < 4; ++p) {
                int r = kvr + (p << 3);
                *(float4*)&Kn[r][kvc] = cvt4(kreg[p]);
                *(float4*)&Vn[r][kvc] = cvt4(vreg[p]);
            }
        }
        __syncthreads();
        buf ^= 1;
    }

    // ---- final normalize + store ----
    float inv0 = 1.f / l0, inv1 = 1.f / l1;
    const int bb = bh >> 3, h = bh & 7;
    int nr0 = q0 + wq + gid;
    float* base0 = g_cat + ((bb * N_ + nr0) * H_ + h) * 128;
    float* base1 = g_cat + ((bb * N_ + nr0 + 8) * H_ + h) * 128;
#pragma unroll
    for (int nt = 0; nt < 8; ++nt) {
        int d = (nt << 3) + (tig << 1);
        *(float2*)(base0 + d) = make_float2(o[nt].x * inv0, o[nt].y * inv0);
        *(float2*)(base1 + d) = make_float2(o[nt].z * inv1, o[nt].w * inv1);
    }
}

// ---------------------------------------------------------------------------
// Kernel 3: out2 = attn2 @ t as two geometric IIR scans per channel.
// Segmented: r^64 = e^{-64/e} ~ 6e-11, so each 256-token segment is computed
// independently with a 64-token warm-up halo (8x parallelism, error ~1e-10).
// ---------------------------------------------------------------------------
#define SEG_  256
#define HALO_ 64
__global__ __launch_bounds__(128) void k_scan()
{
    __shared__ float sinv[N_];
    const int tid = threadIdx.x;
    const float inv_e = 0.36787944117144233f;   // 1/e
    const float r     = 0.69220062755534635f;   // exp(-1/e)
    const float cgeo  = 1.0f / (1.0f - r);
    for (int i = tid; i < N_; i += 128) {
        float s = 1.0f + (r - __expf(-(float)(i + 1) * inv_e)) * cgeo
                       + (r - __expf(-(float)(N_ - i) * inv_e)) * cgeo;
        sinv[i] = 1.0f / s;
    }
    __syncthreads();

    const int gidx = (blockIdx.x << 7) + tid;   // 0..8191
    const int d    = gidx & 63;
    const int rest = gidx >> 6;                 // 0..127
    const int seg  = rest & 7;
    const int bh   = rest >> 3;                 // 0..15
    const int b    = bh >> 3, h = bh & 7;
    const float* tp = g_t + bh * N_ * DH_ + d;
    float* cp = g_cat + (b * N_ * H_) * 128 + h * 128 + 64 + d;
    const int s0 = seg * SEG_;
    const int e0 = s0 + SEG_;

    // Forward scan with halo warm-up.
    float f = 0.f;
    {
        int w0 = (seg == 0) ? 0 : s0 - HALO_;
        for (int i = w0; i < s0; ++i)
            f = fmaf(r, f, tp[i * DH_] * sinv[i]);
    }
    for (int base = s0; base < e0; base += 16) {
        float u[16];
#pragma unroll
        for (int q = 0; q < 16; ++q)
            u[q] = tp[(base + q) * DH_] * sinv[base + q];
#pragma unroll
        for (int q = 0; q < 16; ++q) {
            f = fmaf(r, f, u[q]);
            cp[(base + q) * 1024] = f;
        }
    }

    // Backward scan with halo warm-up (strict upper part).
    float g = 0.f;
    {
        int w1 = (e0 + HALO_ > N_) ? N_ : e0 + HALO_;
        for (int i = w1 - 1; i >= e0; --i)
            g = r * (tp[i * DH_] * sinv[i] + g);
    }
    for (int base = e0 - 16; base >= s0; base -= 16) {
        float u[16];
#pragma unroll
        for (int q = 0; q < 16; ++q)
            u[q] = tp[(base + q) * DH_] * sinv[base + q];
#pragma unroll
        for (int q = 15; q >= 0; --q) {
            cp[(base + q) * 1024] += g;
            g = r * (u[q] + g);
        }
    }
}

// ---------------------------------------------------------------------------
// Kernel 4: out = g_cat[4096,1024] @ W_out[1024,512] + b_out (tf32 MMA,
// double-buffered SMEM + register-staged prefetch).
// ---------------------------------------------------------------------------
__global__ __launch_bounds__(256) void k_gemm_out(const float* __restrict__ W,
                                                  const float* __restrict__ bias,
                                                  float* __restrict__ out)
{
    __shared__ float As[2][128][36];
    __shared__ float Bs[2][32][136];
    const int tid  = threadIdx.x;
    const int lane = tid & 31, warp = tid >> 5;
    const int gid  = lane >> 2, tig = lane & 3;
    const int row0 = blockIdx.y << 7, col0 = blockIdx.x << 7;
    const int wm = (warp & 3) << 5;
    const int wn = (warp >> 2) << 6;

    float4 acc[2][8];
#pragma unroll
    for (int i = 0; i < 2; ++i)
#pragma unroll
        for (int j = 0; j < 8; ++j) acc[i][j] = make_float4(0.f, 0.f, 0.f, 0.f);

    const int ar_ = tid >> 3, ac_ = (tid & 7) << 2;
    const int br_ = tid >> 5, bc_ = (tid & 31) << 2;

    float4 ra[4], rb[4];
#pragma unroll
    for (int p = 0; p < 4; ++p)
        ra[p] = *(const float4*)(g_cat + (row0 + ar_ + (p << 5)) * 1024 + ac_);
#pragma unroll
    for (int p = 0; p < 4; ++p)
        rb[p] = *(const float4*)(W + (br_ + (p << 3)) * 512 + col0 + bc_);
#pragma unroll
    for (int p = 0; p < 4; ++p)
        *(float4*)&As[0][ar_ + (p << 5)][ac_] = cvt4(ra[p]);
#pragma unroll
    for (int p = 0; p < 4; ++p)
        *(float4*)&Bs[0][br_ + (p << 3)][bc_] = cvt4(rb[p]);
    __syncthreads();

    int buf = 0;
    for (int k0 = 0; k0 < 1024; k0 += 32) {
        const bool nxt = (k0 + 32) < 1024;
        if (nxt) {
#pragma unroll
            for (int p = 0; p < 4; ++p)
                ra[p] = *(const float4*)(g_cat + (row0 + ar_ + (p << 5)) * 1024
                                         + k0 + 32 + ac_);
#pragma unroll
            for (int p = 0; p < 4; ++p)
                rb[p] = *(const float4*)(W + (k0 + 32 + br_ + (p << 3)) * 512
                                         + col0 + bc_);
        }
        float (*Ac)[36]  = As[buf];
        float (*Bc)[136] = Bs[buf];
#pragma unroll
        for (int ks = 0; ks < 4; ++ks) {
            const int kk = ks << 3;
            unsigned a[2][4], b[8][2];
#pragma unroll
            for (int mt = 0; mt < 2; ++mt) {
                int r = wm + (mt << 4) + gid;
                a[mt][0] = __float_as_uint(Ac[r][kk + tig]);
                a[mt][1] = __float_as_uint(Ac[r + 8][kk + tig]);
                a[mt][2] = __float_as_uint(Ac[r][kk + tig + 4]);
                a[mt][3] = __float_as_uint(Ac[r + 8][kk + tig + 4]);
            }
#pragma unroll
            for (int nt = 0; nt < 8; ++nt) {
                int c = wn + (nt << 3) + gid;
                b[nt][0] = __float_as_uint(Bc[kk + tig][c]);
                b[nt][1] = __float_as_uint(Bc[kk + tig + 4][c]);
            }
#pragma unroll
            for (int mt = 0; mt < 2; ++mt)
#pragma unroll
                for (int nt = 0; nt < 8; ++nt)
                    mma8(acc[mt][nt], a[mt], b[nt], acc[mt][nt]);
        }
        if (nxt) {
            float (*An)[36]  = As[buf ^ 1];
            float (*Bn)[136] = Bs[buf ^ 1];
#pragma unroll
            for (int p = 0; p < 4; ++p)
                *(float4*)&An[ar_ + (p << 5)][ac_] = cvt4(ra[p]);
#pragma unroll
            for (int p = 0; p < 4; ++p)
                *(float4*)&Bn[br_ + (p << 3)][bc_] = cvt4(rb[p]);
        }
        __syncthreads();
        buf ^= 1;
    }

#pragma unroll
    for (int mt = 0; mt < 2; ++mt) {
        int gr0 = row0 + wm + (mt << 4) + gid;
        int gr1 = gr0 + 8;
#pragma unroll
        for (int nt = 0; nt < 8; ++nt) {
            int gc = col0 + wn + (nt << 3) + (tig << 1);
            float2 bv = *(const float2*)(bias + gc);
            *(float2*)(out + gr0 * 512 + gc)
                = make_float2(acc[mt][nt].x + bv.x, acc[mt][nt].y + bv.y);
            *(float2*)(out + gr1 * 512 + gc)
                = make_float2(acc[mt][nt].z + bv.x, acc[mt][nt].w + bv.y);
        }
    }
}

// ---------------------------------------------------------------------------
extern "C" void kernel_launch(void* const* d_in, const int* in_sizes, int n_in,
                              void* d_out, int out_size)
{
    (void)in_sizes; (void)n_in; (void)out_size;
    const float* x     = (const float*)d_in[0];
    const float* W_qkv = (const float*)d_in[1];
    const float* W_out = (const float*)d_in[2];
    const float* b_out = (const float*)d_in[3];
    float* out = (float*)d_out;

    k_gemm_qkv<<<dim3(16, 32), 256>>>(x, W_qkv);   // qkvt projection (tf32)
    k_attn    <<<dim3(32, 16), 128>>>();           // attn1 flash (tf32, pipelined)
    k_scan    <<<64, 128>>>();                     // attn2 (segmented IIR)
    k_gemm_out<<<dim3(4, 32), 256>>>(W_out, b_out, out);
}